// round 7
// baseline (speedup 1.0000x reference)
#include <cuda_runtime.h>
#include <math.h>
#include <stdint.h>

#define T_DIM 8192
#define D_DIM 512

// Scratch (allocation-free rule: __device__ globals)
__device__ float g_hnorm[T_DIM * D_DIM];
__device__ float g_q[T_DIM * D_DIM];
__device__ float g_k[T_DIM * D_DIM];
__device__ float g_v[T_DIM * D_DIM];
__device__ float g_vt[T_DIM * D_DIM];          // V transposed: [d][T]
__device__ float g_av[T_DIM * D_DIM];
__device__ float g_avp[2][T_DIM * D_DIM];      // PV split-K partials
__device__ float g_wr[4][D_DIM * D_DIM];       // tf32-rounded weights
__device__ float g_S[(size_t)T_DIM * T_DIM];   // 256 MB score matrix

// ===========================================================================
// Helpers
// ===========================================================================
__device__ __forceinline__ uint32_t smem_u32(const void* p) {
    uint32_t a;
    asm("{ .reg .u64 t; cvta.to.shared.u64 t, %1; cvt.u32.u64 %0, t; }" : "=r"(a) : "l"(p));
    return a;
}
__device__ __forceinline__ float rnd_tf32(float f) {
    uint32_t r;
    asm("cvt.rna.tf32.f32 %0, %1;" : "=r"(r) : "f"(f));
    return __uint_as_float(r);
}
#define SW128(o) ((o) ^ ((((uint32_t)(o)) >> 3) & 0x70))

#define CP_ASYNC16(dst, src) \
    asm volatile("cp.async.cg.shared.global [%0], [%1], 16;" :: "r"(dst), "l"(src) : "memory")
#define CP_COMMIT() asm volatile("cp.async.commit_group;" ::: "memory")
#define CP_WAIT1()  asm volatile("cp.async.wait_group 1;" ::: "memory")

__device__ __forceinline__ void ldsm_x4(uint32_t& r0, uint32_t& r1, uint32_t& r2, uint32_t& r3,
                                        uint32_t addr) {
    asm volatile("ldmatrix.sync.aligned.m8n8.x4.shared.b16 {%0,%1,%2,%3}, [%4];"
                 : "=r"(r0), "=r"(r1), "=r"(r2), "=r"(r3) : "r"(addr));
}

__device__ __forceinline__ void mma_tf32(float* c, const uint32_t* a, const uint32_t* b) {
    asm volatile(
        "mma.sync.aligned.m16n8k8.row.col.f32.tf32.tf32.f32 "
        "{%0,%1,%2,%3}, {%4,%5,%6,%7}, {%8,%9}, {%0,%1,%2,%3};"
        : "+f"(c[0]), "+f"(c[1]), "+f"(c[2]), "+f"(c[3])
        : "r"(a[0]), "r"(a[1]), "r"(a[2]), "r"(a[3]),
          "r"(b[0]), "r"(b[1]));
}

// ===========================================================================
// Round all 4 weight matrices to tf32 grid in one launch (blockIdx.y picks)
// ===========================================================================
__global__ void round_weights_kernel(const float* __restrict__ w0,
                                     const float* __restrict__ w1,
                                     const float* __restrict__ w2,
                                     const float* __restrict__ w3,
                                     float* __restrict__ out)
{
    const float* src = (blockIdx.y == 0) ? w0 : (blockIdx.y == 1) ? w1
                     : (blockIdx.y == 2) ? w2 : w3;
    float* dst = out + (size_t)blockIdx.y * D_DIM * D_DIM;
    int i = blockIdx.x * 256 + threadIdx.x;
    float4 v = ((const float4*)src)[i];
    float4 o;
    o.x = rnd_tf32(v.x); o.y = rnd_tf32(v.y); o.z = rnd_tf32(v.z); o.w = rnd_tf32(v.w);
    ((float4*)dst)[i] = o;
}

// ===========================================================================
// Reduce PV split-K partials: av = rnd_tf32(p0 + p1)
// ===========================================================================
__global__ void reduce_av_kernel(const float* __restrict__ p, float* __restrict__ out)
{
    int i = blockIdx.x * 256 + threadIdx.x;
    float4 a = ((const float4*)p)[i];
    float4 b = ((const float4*)(p + (size_t)T_DIM * D_DIM))[i];
    float4 o;
    o.x = rnd_tf32(a.x + b.x);
    o.y = rnd_tf32(a.y + b.y);
    o.z = rnd_tf32(a.z + b.z);
    o.w = rnd_tf32(a.w + b.w);
    ((float4*)out)[i] = o;
}

// ===========================================================================
// LayerNorm: one block (128 threads) per row; output rounded to tf32 grid
// ===========================================================================
__global__ void ln_kernel(const float* __restrict__ h,
                          const float* __restrict__ w,
                          const float* __restrict__ b,
                          float* __restrict__ out)
{
    int row = blockIdx.x;
    int t = threadIdx.x;
    const float4* hr = (const float4*)(h + (size_t)row * D_DIM);
    float4 x = hr[t];
    float s  = x.x + x.y + x.z + x.w;
    float ss = x.x * x.x + x.y * x.y + x.z * x.z + x.w * x.w;

    #pragma unroll
    for (int o = 16; o; o >>= 1) {
        s  += __shfl_xor_sync(0xffffffffu, s,  o);
        ss += __shfl_xor_sync(0xffffffffu, ss, o);
    }
    __shared__ float red[2][4];
    int lane = t & 31, warp = t >> 5;
    if (lane == 0) { red[0][warp] = s; red[1][warp] = ss; }
    __syncthreads();
    float a = red[0][0] + red[0][1] + red[0][2] + red[0][3];
    float c = red[1][0] + red[1][1] + red[1][2] + red[1][3];
    float mean = a * (1.0f / D_DIM);
    float var  = c * (1.0f / D_DIM) - mean * mean;
    float rstd = rsqrtf(var + 1e-5f);

    float4 wv = ((const float4*)w)[t];
    float4 bv = ((const float4*)b)[t];
    float4 o;
    o.x = rnd_tf32((x.x - mean) * rstd * wv.x + bv.x);
    o.y = rnd_tf32((x.y - mean) * rstd * wv.y + bv.y);
    o.z = rnd_tf32((x.z - mean) * rstd * wv.z + bv.z);
    o.w = rnd_tf32((x.w - mean) * rstd * wv.w + bv.w);
    ((float4*)(out + (size_t)row * D_DIM))[t] = o;
}

// ===========================================================================
// 32x32 tiled transpose: out[d][T] = in[T][d]
// ===========================================================================
__global__ void transpose_kernel(const float* __restrict__ in, float* __restrict__ out)
{
    __shared__ float tile[32][33];
    int x0 = blockIdx.x * 32;   // d
    int y0 = blockIdx.y * 32;   // T
    int tx = threadIdx.x & 31, ty = threadIdx.x >> 5;   // 32 x 8
    #pragma unroll
    for (int i = 0; i < 32; i += 8)
        tile[ty + i][tx] = in[(size_t)(y0 + ty + i) * D_DIM + x0 + tx];
    __syncthreads();
    #pragma unroll
    for (int i = 0; i < 32; i += 8)
        out[(size_t)(x0 + ty + i) * T_DIM + y0 + tx] = tile[tx][ty + i];
}

// ===========================================================================
// TF32 mma.sync GEMM (NT): C[M,N] = scale*(A[M,K] @ B[N,K]^T) (+res)
// 128x256x32 block tile, 8 warps (2x4), warp tile 64x64.
// 3-stage cp.async ring (SW128-swizzled 128B rows), ldmatrix fragments with
// cross-slice double buffering (prefetch slice s+1 during MMAs of slice s).
// Operands pre-rounded to tf32 grid by producers (MMA truncation exact).
//   CAUSAL=1: skip blocks fully above diagonal
//   CAPK=1:   cap k-loop at m0+128 (PV over zero-padded causal probs)
//   ROUND=1:  round outputs to tf32 grid (outputs feed another MMA)
//   RES=1:    add residual (final output)
//   KSPLIT>0: split k-range across blockIdx.z, raw partial to C + z*M*ldc
// ===========================================================================
#define BK 32
#define BNT 256
#define TILE_A_B (128 * BK * 4)     // 16 KB
#define TILE_B_B (BNT * BK * 4)     // 32 KB
#define NSTAGE 3
#define SM_A 0
#define SM_B (NSTAGE * TILE_A_B)
#define SM_TOT (NSTAGE * (TILE_A_B + TILE_B_B))   // 144 KB

template<int CAUSAL, int CAPK, int ROUND, int RES, int KSPLIT>
__global__ void __launch_bounds__(256, 1)
gemm_nt_tc(const float* __restrict__ A,
           const float* __restrict__ B,
           float* __restrict__ C,
           const float* __restrict__ res,
           int M, int N, int K,
           int lda, int ldb, int ldc,
           float scale)
{
    extern __shared__ char smem[];
    int m0 = blockIdx.y * 128;
    int n0 = blockIdx.x * BNT;
    if (CAUSAL && n0 > m0 + 127) return;

    uint32_t sbase = smem_u32(smem);
    int t    = threadIdx.x;          // 0..255
    int lane = t & 31;
    int warp = t >> 5;               // 0..7
    int gid  = lane >> 2;
    int tig  = lane & 3;
    int wm   = (warp >> 2) * 64;     // 0,64
    int wn   = (warp & 3) * 64;      // 0..192

    int kend  = CAPK ? min(K, m0 + 128) : K;
    int iters = kend / BK;
    int it0 = 0, it1 = iters;
    if (KSPLIT > 0) {
        int z = blockIdx.z;
        it0 = (iters * z) / KSPLIT;
        it1 = (iters * (z + 1)) / KSPLIT;
        C += (size_t)blockIdx.z * M * ldc;
    }
    int niter = it1 - it0;

    auto load_tiles = [&](int buf, int k0) {
        #pragma unroll
        for (int i = 0; i < 4; i++) {
            int f = t + i * 256;
            int row = f >> 3, kg = f & 7;
            uint32_t off = SW128((uint32_t)(row * 128 + kg * 16));
            CP_ASYNC16(sbase + SM_A + buf * TILE_A_B + off,
                       A + (size_t)(m0 + row) * lda + k0 + kg * 4);
        }
        #pragma unroll
        for (int i = 0; i < 8; i++) {
            int f = t + i * 256;
            int row = f >> 3, kg = f & 7;
            uint32_t off = SW128((uint32_t)(row * 128 + kg * 16));
            CP_ASYNC16(sbase + SM_B + buf * TILE_B_B + off,
                       B + (size_t)(n0 + row) * ldb + k0 + kg * 4);
        }
    };

    float acc[4][8][4];
    #pragma unroll
    for (int mi = 0; mi < 4; mi++)
        #pragma unroll
        for (int ni = 0; ni < 8; ni++)
            #pragma unroll
            for (int r = 0; r < 4; r++) acc[mi][ni][r] = 0.0f;

    // per-thread ldmatrix address components
    int q   = lane >> 3;          // tile index within x4 (0..3)
    int r8  = lane & 7;           // row within tile
    int aq1 = (q & 1) * 8;        // A: +8 rows for tiles 1,3
    int aq2 = q >> 1;             // A: kg +1 for tiles 2,3
    int bq1 = (q >> 1) * 8;       // B: second n-tile for tiles 2,3
    int bq2 = q & 1;              // B: kg +1 for tiles 1,3

    uint32_t afr[2][4][4];
    uint32_t bfr[2][8][2];

    auto load_frag = [&](uint32_t sa, uint32_t sb, int ks, int pb) {
        #pragma unroll
        for (int mi = 0; mi < 4; mi++) {
            int row = wm + mi * 16 + aq1 + r8;
            int kg  = 2 * ks + aq2;
            uint32_t addr = sa + (uint32_t)(row * 128) + (uint32_t)((kg ^ r8) * 16);
            ldsm_x4(afr[pb][mi][0], afr[pb][mi][1], afr[pb][mi][2], afr[pb][mi][3], addr);
        }
        #pragma unroll
        for (int p = 0; p < 4; p++) {
            int row = wn + p * 16 + bq1 + r8;
            int kg  = 2 * ks + bq2;
            uint32_t addr = sb + (uint32_t)(row * 128) + (uint32_t)((kg ^ r8) * 16);
            ldsm_x4(bfr[pb][2 * p][0], bfr[pb][2 * p][1],
                    bfr[pb][2 * p + 1][0], bfr[pb][2 * p + 1][1], addr);
        }
    };

    // prologue: stage first two tiles
    load_tiles(0, it0 * BK);
    CP_COMMIT();
    if (niter > 1) load_tiles(1, (it0 + 1) * BK);
    CP_COMMIT();

    int buf = 0;
    for (int it = 0; it < niter; it++) {
        CP_WAIT1();
        __syncthreads();

        uint32_t sa = sbase + SM_A + buf * TILE_A_B;
        uint32_t sb = sbase + SM_B + buf * TILE_B_B;

        // issue next-next tile load into the free buffer
        int nx = it + 2;
        int nbuf = buf + 2; if (nbuf >= NSTAGE) nbuf -= NSTAGE;
        if (nx < niter) load_tiles(nbuf, (it0 + nx) * BK);
        CP_COMMIT();

        // fragment-pipelined compute over 4 k8-slices
        load_frag(sa, sb, 0, 0);
        #pragma unroll
        for (int ks = 0; ks < BK / 8; ks++) {
            int cur = ks & 1;
            if (ks + 1 < BK / 8) load_frag(sa, sb, ks + 1, cur ^ 1);
            #pragma unroll
            for (int mi = 0; mi < 4; mi++)
                #pragma unroll
                for (int ni = 0; ni < 8; ni++)
                    mma_tf32(acc[mi][ni], afr[cur][mi], bfr[cur][ni]);
        }

        buf++; if (buf >= NSTAGE) buf = 0;
    }

    // epilogue
    #pragma unroll
    for (int mi = 0; mi < 4; mi++) {
        #pragma unroll
        for (int ni = 0; ni < 8; ni++) {
            int row = m0 + wm + mi * 16 + gid;
            int col = n0 + wn + ni * 8 + tig * 2;
            float2 o0, o1;
            o0.x = acc[mi][ni][0]; o0.y = acc[mi][ni][1];
            o1.x = acc[mi][ni][2]; o1.y = acc[mi][ni][3];
            if (!KSPLIT) {
                o0.x *= scale; o0.y *= scale; o1.x *= scale; o1.y *= scale;
            }
            size_t i0 = (size_t)row * ldc + col;
            size_t i1 = (size_t)(row + 8) * ldc + col;
            if (RES) {
                float2 r0 = *(const float2*)(res + i0);
                float2 r1 = *(const float2*)(res + i1);
                o0.x += r0.x; o0.y += r0.y;
                o1.x += r1.x; o1.y += r1.y;
            }
            if (ROUND) {
                o0.x = rnd_tf32(o0.x); o0.y = rnd_tf32(o0.y);
                o1.x = rnd_tf32(o1.x); o1.y = rnd_tf32(o1.y);
            }
            *(float2*)(C + i0) = o0;
            *(float2*)(C + i1) = o1;
        }
    }
}

// ===========================================================================
// Causal row softmax over S (in place), float4 + __expf.
// Output probs rounded to tf32 grid; zero-pads to next 128-col boundary.
// ===========================================================================
__device__ __forceinline__ float block_reduce(float v, bool is_max)
{
    __shared__ float sm[8];
    __syncthreads();
    #pragma unroll
    for (int o = 16; o; o >>= 1) {
        float u = __shfl_xor_sync(0xffffffffu, v, o);
        v = is_max ? fmaxf(v, u) : (v + u);
    }
    int lane = threadIdx.x & 31, warp = threadIdx.x >> 5;
    if (lane == 0) sm[warp] = v;
    __syncthreads();
    float r = sm[0];
    #pragma unroll
    for (int i = 1; i < 8; i++)
        r = is_max ? fmaxf(r, sm[i]) : (r + sm[i]);
    return r;
}

__global__ void softmax_causal(float* __restrict__ S)
{
    int row = blockIdx.x;
    int t = threadIdx.x;               // 0..255
    int n = row + 1;
    float4* Srow = (float4*)(S + (size_t)row * T_DIM);

    float4 v[8];
    float mx = -INFINITY;
    #pragma unroll
    for (int it = 0; it < 8; it++) {
        int j0 = ((it << 8) + t) << 2;
        float4 x = (j0 < n) ? Srow[(it << 8) + t]
                            : make_float4(-INFINITY, -INFINITY, -INFINITY, -INFINITY);
        if (j0 + 1 >= n) x.y = -INFINITY;
        if (j0 + 2 >= n) x.z = -INFINITY;
        if (j0 + 3 >= n) x.w = -INFINITY;
        v[it] = x;
        mx = fmaxf(mx, fmaxf(fmaxf(x.x, x.y), fmaxf(x.z, x.w)));
    }
    mx = block_reduce(mx, true);

    float sum = 0.0f;
    #pragma unroll
    for (int it = 0; it < 8; it++) {
        float4 x = v[it];
        x.x = (x.x == -INFINITY) ? 0.0f : __expf(x.x - mx);
        x.y = (x.y == -INFINITY) ? 0.0f : __expf(x.y - mx);
        x.z = (x.z == -INFINITY) ? 0.0f : __expf(x.z - mx);
        x.w = (x.w == -INFINITY) ? 0.0f : __expf(x.w - mx);
        v[it] = x;
        sum += x.x + x.y + x.z + x.w;
    }
    sum = block_reduce(sum, false);
    float inv = 1.0f / sum;

    int zend = (n + 127) & ~127;
    #pragma unroll
    for (int it = 0; it < 8; it++) {
        int j0 = ((it << 8) + t) << 2;
        if (j0 < zend) {
            float4 x = v[it];
            float4 o;
            o.x = rnd_tf32(x.x * inv);
            o.y = rnd_tf32(x.y * inv);
            o.z = rnd_tf32(x.z * inv);
            o.w = rnd_tf32(x.w * inv);
            Srow[(it << 8) + t] = o;
        }
    }
}

// ===========================================================================
extern "C" void kernel_launch(void* const* d_in, const int* in_sizes, int n_in,
                              void* d_out, int out_size)
{
    const float* h    = (const float*)d_in[0];
    const float* ln_w = (const float*)d_in[1];
    const float* ln_b = (const float*)d_in[2];
    const float* w_q  = (const float*)d_in[3];
    const float* w_k  = (const float*)d_in[4];
    const float* w_v  = (const float*)d_in[5];
    const float* w_o  = (const float*)d_in[6];
    float* out = (float*)d_out;

    float *hn, *q, *k, *v, *vt, *av, *avp, *S, *wr;
    cudaGetSymbolAddress((void**)&hn,  g_hnorm);
    cudaGetSymbolAddress((void**)&q,   g_q);
    cudaGetSymbolAddress((void**)&k,   g_k);
    cudaGetSymbolAddress((void**)&v,   g_v);
    cudaGetSymbolAddress((void**)&vt,  g_vt);
    cudaGetSymbolAddress((void**)&av,  g_av);
    cudaGetSymbolAddress((void**)&avp, g_avp);
    cudaGetSymbolAddress((void**)&S,   g_S);
    cudaGetSymbolAddress((void**)&wr,  g_wr);
    float* wq_r = wr;
    float* wk_r = wr + 1 * D_DIM * D_DIM;
    float* wv_r = wr + 2 * D_DIM * D_DIM;
    float* wo_r = wr + 3 * D_DIM * D_DIM;

    cudaFuncSetAttribute((const void*)gemm_nt_tc<0,0,1,0,0>,
                         cudaFuncAttributeMaxDynamicSharedMemorySize, SM_TOT);
    cudaFuncSetAttribute((const void*)gemm_nt_tc<1,0,0,0,0>,
                         cudaFuncAttributeMaxDynamicSharedMemorySize, SM_TOT);
    cudaFuncSetAttribute((const void*)gemm_nt_tc<0,1,0,0,2>,
                         cudaFuncAttributeMaxDynamicSharedMemorySize, SM_TOT);
    cudaFuncSetAttribute((const void*)gemm_nt_tc<0,0,0,1,0>,
                         cudaFuncAttributeMaxDynamicSharedMemorySize, SM_TOT);

    const float inv_sqrt_d = 0.044194173824159216f;  // 1/sqrt(512)

    // 0) Round weights to tf32 grid (single launch)
    dim3 gW((D_DIM * D_DIM) / 4 / 256, 4);
    round_weights_kernel<<<gW, 256>>>(w_q, w_k, w_v, w_o, wr);

    // 1) LayerNorm (tf32-rounded output)
    ln_kernel<<<T_DIM, 128>>>(h, ln_w, ln_b, hn);

    // 2) Q, K, V projections (NT, rounded outputs)
    dim3 gProj(D_DIM / BNT, T_DIM / 128);  // (2, 64)
    gemm_nt_tc<0,0,1,0,0><<<gProj, 256, SM_TOT>>>(hn, wq_r, q, nullptr,
        T_DIM, D_DIM, D_DIM, D_DIM, D_DIM, D_DIM, 1.0f);
    gemm_nt_tc<0,0,1,0,0><<<gProj, 256, SM_TOT>>>(hn, wk_r, k, nullptr,
        T_DIM, D_DIM, D_DIM, D_DIM, D_DIM, D_DIM, 1.0f);
    gemm_nt_tc<0,0,1,0,0><<<gProj, 256, SM_TOT>>>(hn, wv_r, v, nullptr,
        T_DIM, D_DIM, D_DIM, D_DIM, D_DIM, D_DIM, 1.0f);

    // 2b) Transpose V -> Vt[d][T] (already rounded)
    dim3 gT(D_DIM / 32, T_DIM / 32);   // (16, 256)
    transpose_kernel<<<gT, 256>>>(v, vt);

    // 3) Scores = Q @ K^T * 1/sqrt(d), lower-tri blocks only (NT, causal)
    dim3 gScore(T_DIM / BNT, T_DIM / 128);  // (32, 64)
    gemm_nt_tc<1,0,0,0,0><<<gScore, 256, SM_TOT>>>(q, k, S, nullptr,
        T_DIM, T_DIM, D_DIM, D_DIM, D_DIM, T_DIM, inv_sqrt_d);

    // 4) Causal softmax (in place, rounded probs, zero-pads to 128-col)
    softmax_causal<<<T_DIM, 256>>>(S);

    // 5) AV partials = softmax(S) @ Vt^T (NT, k-capped, split-K2)
    dim3 gPV(D_DIM / BNT, T_DIM / 128, 2);  // (2, 64, 2)
    gemm_nt_tc<0,1,0,0,2><<<gPV, 256, SM_TOT>>>(S, vt, avp, nullptr,
        T_DIM, D_DIM, T_DIM, T_DIM, T_DIM, D_DIM, 1.0f);

    // 5b) av = rnd_tf32(p0 + p1)
    reduce_av_kernel<<<(T_DIM * D_DIM) / 4 / 256, 256>>>(avp, av);

    // 6) out = h + AV @ W_o^T (NT with residual)
    gemm_nt_tc<0,0,0,1,0><<<gProj, 256, SM_TOT>>>(av, wo_r, out, h,
        T_DIM, D_DIM, D_DIM, D_DIM, D_DIM, D_DIM, 1.0f);
}

// round 8
// speedup vs baseline: 1.1098x; 1.1098x over previous
#include <cuda_runtime.h>
#include <math.h>
#include <stdint.h>

#define T_DIM 8192
#define D_DIM 512

// Scratch (allocation-free rule: __device__ globals)
__device__ float g_hnorm[T_DIM * D_DIM];
__device__ float g_q[T_DIM * D_DIM];
__device__ float g_k[T_DIM * D_DIM];
__device__ float g_vt[T_DIM * D_DIM];          // V transposed: [d][T]
__device__ float g_avp[2][T_DIM * D_DIM];      // PV split-K partials
__device__ float g_wr[4][D_DIM * D_DIM];       // tf32-rounded weights
__device__ float g_S[(size_t)T_DIM * T_DIM];   // 256 MB score matrix

// ===========================================================================
// Helpers
// ===========================================================================
__device__ __forceinline__ uint32_t smem_u32(const void* p) {
    uint32_t a;
    asm("{ .reg .u64 t; cvta.to.shared.u64 t, %1; cvt.u32.u64 %0, t; }" : "=r"(a) : "l"(p));
    return a;
}
__device__ __forceinline__ float rnd_tf32(float f) {
    uint32_t r;
    asm("cvt.rna.tf32.f32 %0, %1;" : "=r"(r) : "f"(f));
    return __uint_as_float(r);
}
#define SW128(o) ((o) ^ ((((uint32_t)(o)) >> 3) & 0x70))

#define CP_ASYNC16(dst, src) \
    asm volatile("cp.async.cg.shared.global [%0], [%1], 16;" :: "r"(dst), "l"(src) : "memory")
#define CP_COMMIT() asm volatile("cp.async.commit_group;" ::: "memory")
#define CP_WAIT1()  asm volatile("cp.async.wait_group 1;" ::: "memory")

__device__ __forceinline__ void ldsm_x4(uint32_t& r0, uint32_t& r1, uint32_t& r2, uint32_t& r3,
                                        uint32_t addr) {
    asm volatile("ldmatrix.sync.aligned.m8n8.x4.shared.b16 {%0,%1,%2,%3}, [%4];"
                 : "=r"(r0), "=r"(r1), "=r"(r2), "=r"(r3) : "r"(addr));
}

__device__ __forceinline__ void mma_tf32(float* c, const uint32_t* a, const uint32_t* b) {
    asm volatile(
        "mma.sync.aligned.m16n8k8.row.col.f32.tf32.tf32.f32 "
        "{%0,%1,%2,%3}, {%4,%5,%6,%7}, {%8,%9}, {%0,%1,%2,%3};"
        : "+f"(c[0]), "+f"(c[1]), "+f"(c[2]), "+f"(c[3])
        : "r"(a[0]), "r"(a[1]), "r"(a[2]), "r"(a[3]),
          "r"(b[0]), "r"(b[1]));
}

// ===========================================================================
// Round all 4 weight matrices to tf32 grid in one launch (blockIdx.y picks)
// ===========================================================================
__global__ void round_weights_kernel(const float* __restrict__ w0,
                                     const float* __restrict__ w1,
                                     const float* __restrict__ w2,
                                     const float* __restrict__ w3,
                                     float* __restrict__ out)
{
    const float* src = (blockIdx.y == 0) ? w0 : (blockIdx.y == 1) ? w1
                     : (blockIdx.y == 2) ? w2 : w3;
    float* dst = out + (size_t)blockIdx.y * D_DIM * D_DIM;
    int i = blockIdx.x * 256 + threadIdx.x;
    float4 v = ((const float4*)src)[i];
    float4 o;
    o.x = rnd_tf32(v.x); o.y = rnd_tf32(v.y); o.z = rnd_tf32(v.z); o.w = rnd_tf32(v.w);
    ((float4*)dst)[i] = o;
}

// ===========================================================================
// LayerNorm: one block (128 threads) per row; output rounded to tf32 grid
// ===========================================================================
__global__ void ln_kernel(const float* __restrict__ h,
                          const float* __restrict__ w,
                          const float* __restrict__ b,
                          float* __restrict__ out)
{
    int row = blockIdx.x;
    int t = threadIdx.x;
    const float4* hr = (const float4*)(h + (size_t)row * D_DIM);
    float4 x = hr[t];
    float s  = x.x + x.y + x.z + x.w;
    float ss = x.x * x.x + x.y * x.y + x.z * x.z + x.w * x.w;

    #pragma unroll
    for (int o = 16; o; o >>= 1) {
        s  += __shfl_xor_sync(0xffffffffu, s,  o);
        ss += __shfl_xor_sync(0xffffffffu, ss, o);
    }
    __shared__ float red[2][4];
    int lane = t & 31, warp = t >> 5;
    if (lane == 0) { red[0][warp] = s; red[1][warp] = ss; }
    __syncthreads();
    float a = red[0][0] + red[0][1] + red[0][2] + red[0][3];
    float c = red[1][0] + red[1][1] + red[1][2] + red[1][3];
    float mean = a * (1.0f / D_DIM);
    float var  = c * (1.0f / D_DIM) - mean * mean;
    float rstd = rsqrtf(var + 1e-5f);

    float4 wv = ((const float4*)w)[t];
    float4 bv = ((const float4*)b)[t];
    float4 o;
    o.x = rnd_tf32((x.x - mean) * rstd * wv.x + bv.x);
    o.y = rnd_tf32((x.y - mean) * rstd * wv.y + bv.y);
    o.z = rnd_tf32((x.z - mean) * rstd * wv.z + bv.z);
    o.w = rnd_tf32((x.w - mean) * rstd * wv.w + bv.w);
    ((float4*)(out + (size_t)row * D_DIM))[t] = o;
}

// ===========================================================================
// TF32 mma.sync GEMM (NT): C[M,N] = scale*(A[M,K] @ B[N,K]^T) (+res)
// 128x128x32 block tile, 4 warps (2x2), warp tile 64x64 (R6 config, 2 CTA/SM).
// 3-stage cp.async ring (SW128-swizzled 128B rows), ldmatrix frags.
// Operands pre-rounded to tf32 grid by producers (MMA truncation exact).
//   CAUSAL=1: skip blocks fully above diagonal
//   CAPK=1:   cap k-loop at m0+128 (PV over zero-padded causal probs)
//   ROUND=1:  round outputs to tf32 grid (outputs feed another MMA)
//   RES=1:    add residual (final output)
//   KSPLIT>0: split k-range across blockIdx.z, raw partial to C + z*M*ldc
//   WRITET=1: write OUTPUT TRANSPOSED (C[n][m], ldc = row stride in m-dim),
//             rounded to tf32 grid (used by V projection -> vt)
//   SUM2=1:   A operand = rnd_tf32(A[i] + A2[i]) (fused split-K reduce)
// ===========================================================================
#define BK 32
#define TILE_B (128 * BK * 4)    // 16 KB per tile buffer
#define NSTAGE 3
#define SM_A 0
#define SM_B (NSTAGE * TILE_B)
#define SM_TOT (2 * NSTAGE * TILE_B)   // 96 KB

template<int CAUSAL, int CAPK, int ROUND, int RES, int KSPLIT, int WRITET, int SUM2>
__global__ void __launch_bounds__(128, 2)
gemm_nt_tc(const float* __restrict__ A,
           const float* __restrict__ A2,
           const float* __restrict__ B,
           float* __restrict__ C,
           const float* __restrict__ res,
           int M, int N, int K,
           int lda, int ldb, int ldc,
           float scale)
{
    extern __shared__ char smem[];
    int m0 = blockIdx.y * 128;
    int n0 = blockIdx.x * 128;
    if (CAUSAL && n0 > m0 + 127) return;

    uint32_t sbase = smem_u32(smem);
    int t    = threadIdx.x;          // 0..127
    int lane = t & 31;
    int warp = t >> 5;               // 0..3
    int gid  = lane >> 2;
    int tig  = lane & 3;
    int wm   = (warp >> 1) * 64;     // 0,64
    int wn   = (warp & 1) * 64;      // 0,64

    int kend  = CAPK ? min(K, m0 + 128) : K;
    int iters = kend / BK;
    int it0 = 0, it1 = iters;
    if (KSPLIT > 0) {
        int z = blockIdx.z;
        it0 = (iters * z) / KSPLIT;
        it1 = (iters * (z + 1)) / KSPLIT;
        C += (size_t)blockIdx.z * M * ldc;
    }
    int niter = it1 - it0;

    auto load_tiles = [&](int buf, int k0) {
        if (SUM2) {
            #pragma unroll
            for (int i = 0; i < 8; i++) {
                int f = t + i * 128;
                int row = f >> 3, kg = f & 7;
                size_t gidx = (size_t)(m0 + row) * lda + k0 + kg * 4;
                float4 a = *(const float4*)(A + gidx);
                float4 b = *(const float4*)(A2 + gidx);
                float4 o;
                o.x = rnd_tf32(a.x + b.x);
                o.y = rnd_tf32(a.y + b.y);
                o.z = rnd_tf32(a.z + b.z);
                o.w = rnd_tf32(a.w + b.w);
                uint32_t off = SW128((uint32_t)(row * 128 + kg * 16));
                *(float4*)(smem + SM_A + buf * TILE_B + off) = o;
            }
        } else {
            #pragma unroll
            for (int i = 0; i < 8; i++) {
                int f = t + i * 128;
                int row = f >> 3, kg = f & 7;
                uint32_t off = SW128((uint32_t)(row * 128 + kg * 16));
                CP_ASYNC16(sbase + SM_A + buf * TILE_B + off,
                           A + (size_t)(m0 + row) * lda + k0 + kg * 4);
            }
        }
        #pragma unroll
        for (int i = 0; i < 8; i++) {
            int f = t + i * 128;
            int row = f >> 3, kg = f & 7;
            uint32_t off = SW128((uint32_t)(row * 128 + kg * 16));
            CP_ASYNC16(sbase + SM_B + buf * TILE_B + off,
                       B + (size_t)(n0 + row) * ldb + k0 + kg * 4);
        }
    };

    float acc[4][8][4];
    #pragma unroll
    for (int mi = 0; mi < 4; mi++)
        #pragma unroll
        for (int ni = 0; ni < 8; ni++)
            #pragma unroll
            for (int r = 0; r < 4; r++) acc[mi][ni][r] = 0.0f;

    // per-thread ldmatrix address components
    int q   = lane >> 3;          // tile index within x4 (0..3)
    int r8  = lane & 7;           // row within tile
    int aq1 = (q & 1) * 8;        // A: +8 rows for tiles 1,3
    int aq2 = q >> 1;             // A: kg +1 for tiles 2,3
    int bq1 = (q >> 1) * 8;       // B: second n-tile for tiles 2,3
    int bq2 = q & 1;              // B: kg +1 for tiles 1,3

    // prologue: stage first two tiles
    load_tiles(0, it0 * BK);
    CP_COMMIT();
    if (niter > 1) load_tiles(1, (it0 + 1) * BK);
    CP_COMMIT();

    int buf = 0;
    for (int it = 0; it < niter; it++) {
        CP_WAIT1();
        __syncthreads();

        uint32_t sa = sbase + SM_A + buf * TILE_B;
        uint32_t sb = sbase + SM_B + buf * TILE_B;

        // issue next-next tile load into the free buffer
        int nx = it + 2;
        int nbuf = buf + 2; if (nbuf >= NSTAGE) nbuf -= NSTAGE;
        if (nx < niter) load_tiles(nbuf, (it0 + nx) * BK);
        CP_COMMIT();

        #pragma unroll
        for (int ks = 0; ks < BK / 8; ks++) {
            uint32_t afr[4][4];
            #pragma unroll
            for (int mi = 0; mi < 4; mi++) {
                int row = wm + mi * 16 + aq1 + r8;
                int kg  = 2 * ks + aq2;
                uint32_t addr = sa + (uint32_t)(row * 128) + (uint32_t)((kg ^ r8) * 16);
                ldsm_x4(afr[mi][0], afr[mi][1], afr[mi][2], afr[mi][3], addr);
            }
            uint32_t bfr[8][2];
            #pragma unroll
            for (int p = 0; p < 4; p++) {
                int row = wn + p * 16 + bq1 + r8;
                int kg  = 2 * ks + bq2;
                uint32_t addr = sb + (uint32_t)(row * 128) + (uint32_t)((kg ^ r8) * 16);
                uint32_t r0, r1, r2, r3;
                ldsm_x4(r0, r1, r2, r3, addr);
                bfr[2 * p][0] = r0; bfr[2 * p][1] = r1;
                bfr[2 * p + 1][0] = r2; bfr[2 * p + 1][1] = r3;
            }
            #pragma unroll
            for (int mi = 0; mi < 4; mi++)
                #pragma unroll
                for (int ni = 0; ni < 8; ni++)
                    mma_tf32(acc[mi][ni], afr[mi], bfr[ni]);
        }

        buf++; if (buf >= NSTAGE) buf = 0;
    }

    if (WRITET) {
        // Transposed output: stage tile transposed in smem, then coalesced
        // float4 writes of C[n][m] rows. Output rounded to tf32 grid.
        __syncthreads();                 // mainloop smem reads complete
        float* st = (float*)smem;        // 128 cols x stride 132 (67.6 KB)
        #pragma unroll
        for (int mi = 0; mi < 4; mi++) {
            #pragma unroll
            for (int ni = 0; ni < 8; ni++) {
                int row = wm + mi * 16 + gid;
                int col = wn + ni * 8 + tig * 2;
                st[(col + 0) * 132 + row]     = rnd_tf32(acc[mi][ni][0]);
                st[(col + 1) * 132 + row]     = rnd_tf32(acc[mi][ni][1]);
                st[(col + 0) * 132 + row + 8] = rnd_tf32(acc[mi][ni][2]);
                st[(col + 1) * 132 + row + 8] = rnd_tf32(acc[mi][ni][3]);
            }
        }
        __syncthreads();
        #pragma unroll
        for (int i = 0; i < 32; i++) {
            int idx = t + i * 128;       // 4096 float4 writes total
            int d = idx >> 5;            // output row (n-dim), 0..127
            int j = idx & 31;            // float4 index along m
            float4 o = *(float4*)&st[d * 132 + 4 * j];
            *(float4*)(C + (size_t)(n0 + d) * ldc + m0 + 4 * j) = o;
        }
        return;
    }

    // normal epilogue
    #pragma unroll
    for (int mi = 0; mi < 4; mi++) {
        #pragma unroll
        for (int ni = 0; ni < 8; ni++) {
            int row = m0 + wm + mi * 16 + gid;
            int col = n0 + wn + ni * 8 + tig * 2;
            float2 o0, o1;
            o0.x = acc[mi][ni][0]; o0.y = acc[mi][ni][1];
            o1.x = acc[mi][ni][2]; o1.y = acc[mi][ni][3];
            if (!KSPLIT) {
                o0.x *= scale; o0.y *= scale; o1.x *= scale; o1.y *= scale;
            }
            size_t i0 = (size_t)row * ldc + col;
            size_t i1 = (size_t)(row + 8) * ldc + col;
            if (RES) {
                float2 r0 = *(const float2*)(res + i0);
                float2 r1 = *(const float2*)(res + i1);
                o0.x += r0.x; o0.y += r0.y;
                o1.x += r1.x; o1.y += r1.y;
            }
            if (ROUND) {
                o0.x = rnd_tf32(o0.x); o0.y = rnd_tf32(o0.y);
                o1.x = rnd_tf32(o1.x); o1.y = rnd_tf32(o1.y);
            }
            *(float2*)(C + i0) = o0;
            *(float2*)(C + i1) = o1;
        }
    }
}

// ===========================================================================
// Causal row softmax over S (in place), float4 + __expf.
// Output probs rounded to tf32 grid; zero-pads to next 128-col boundary.
// ===========================================================================
__device__ __forceinline__ float block_reduce(float v, bool is_max)
{
    __shared__ float sm[8];
    __syncthreads();
    #pragma unroll
    for (int o = 16; o; o >>= 1) {
        float u = __shfl_xor_sync(0xffffffffu, v, o);
        v = is_max ? fmaxf(v, u) : (v + u);
    }
    int lane = threadIdx.x & 31, warp = threadIdx.x >> 5;
    if (lane == 0) sm[warp] = v;
    __syncthreads();
    float r = sm[0];
    #pragma unroll
    for (int i = 1; i < 8; i++)
        r = is_max ? fmaxf(r, sm[i]) : (r + sm[i]);
    return r;
}

__global__ void softmax_causal(float* __restrict__ S)
{
    int row = blockIdx.x;
    int t = threadIdx.x;               // 0..255
    int n = row + 1;
    float4* Srow = (float4*)(S + (size_t)row * T_DIM);

    float4 v[8];
    float mx = -INFINITY;
    #pragma unroll
    for (int it = 0; it < 8; it++) {
        int j0 = ((it << 8) + t) << 2;
        float4 x = (j0 < n) ? Srow[(it << 8) + t]
                            : make_float4(-INFINITY, -INFINITY, -INFINITY, -INFINITY);
        if (j0 + 1 >= n) x.y = -INFINITY;
        if (j0 + 2 >= n) x.z = -INFINITY;
        if (j0 + 3 >= n) x.w = -INFINITY;
        v[it] = x;
        mx = fmaxf(mx, fmaxf(fmaxf(x.x, x.y), fmaxf(x.z, x.w)));
    }
    mx = block_reduce(mx, true);

    float sum = 0.0f;
    #pragma unroll
    for (int it = 0; it < 8; it++) {
        float4 x = v[it];
        x.x = (x.x == -INFINITY) ? 0.0f : __expf(x.x - mx);
        x.y = (x.y == -INFINITY) ? 0.0f : __expf(x.y - mx);
        x.z = (x.z == -INFINITY) ? 0.0f : __expf(x.z - mx);
        x.w = (x.w == -INFINITY) ? 0.0f : __expf(x.w - mx);
        v[it] = x;
        sum += x.x + x.y + x.z + x.w;
    }
    sum = block_reduce(sum, false);
    float inv = 1.0f / sum;

    int zend = (n + 127) & ~127;
    #pragma unroll
    for (int it = 0; it < 8; it++) {
        int j0 = ((it << 8) + t) << 2;
        if (j0 < zend) {
            float4 x = v[it];
            float4 o;
            o.x = rnd_tf32(x.x * inv);
            o.y = rnd_tf32(x.y * inv);
            o.z = rnd_tf32(x.z * inv);
            o.w = rnd_tf32(x.w * inv);
            Srow[(it << 8) + t] = o;
        }
    }
}

// ===========================================================================
extern "C" void kernel_launch(void* const* d_in, const int* in_sizes, int n_in,
                              void* d_out, int out_size)
{
    const float* h    = (const float*)d_in[0];
    const float* ln_w = (const float*)d_in[1];
    const float* ln_b = (const float*)d_in[2];
    const float* w_q  = (const float*)d_in[3];
    const float* w_k  = (const float*)d_in[4];
    const float* w_v  = (const float*)d_in[5];
    const float* w_o  = (const float*)d_in[6];
    float* out = (float*)d_out;

    float *hn, *q, *k, *vt, *avp, *S, *wr;
    cudaGetSymbolAddress((void**)&hn,  g_hnorm);
    cudaGetSymbolAddress((void**)&q,   g_q);
    cudaGetSymbolAddress((void**)&k,   g_k);
    cudaGetSymbolAddress((void**)&vt,  g_vt);
    cudaGetSymbolAddress((void**)&avp, g_avp);
    cudaGetSymbolAddress((void**)&S,   g_S);
    cudaGetSymbolAddress((void**)&wr,  g_wr);
    float* wq_r = wr;
    float* wk_r = wr + 1 * D_DIM * D_DIM;
    float* wv_r = wr + 2 * D_DIM * D_DIM;
    float* wo_r = wr + 3 * D_DIM * D_DIM;

    cudaFuncSetAttribute((const void*)gemm_nt_tc<0,0,1,0,0,0,0>,
                         cudaFuncAttributeMaxDynamicSharedMemorySize, SM_TOT);
    cudaFuncSetAttribute((const void*)gemm_nt_tc<0,0,1,0,0,1,0>,
                         cudaFuncAttributeMaxDynamicSharedMemorySize, SM_TOT);
    cudaFuncSetAttribute((const void*)gemm_nt_tc<1,0,0,0,0,0,0>,
                         cudaFuncAttributeMaxDynamicSharedMemorySize, SM_TOT);
    cudaFuncSetAttribute((const void*)gemm_nt_tc<0,1,0,0,2,0,0>,
                         cudaFuncAttributeMaxDynamicSharedMemorySize, SM_TOT);
    cudaFuncSetAttribute((const void*)gemm_nt_tc<0,0,0,1,0,0,1>,
                         cudaFuncAttributeMaxDynamicSharedMemorySize, SM_TOT);

    const float inv_sqrt_d = 0.044194173824159216f;  // 1/sqrt(512)

    // 0) Round weights to tf32 grid (single launch)
    dim3 gW((D_DIM * D_DIM) / 4 / 256, 4);
    round_weights_kernel<<<gW, 256>>>(w_q, w_k, w_v, w_o, wr);

    // 1) LayerNorm (tf32-rounded output)
    ln_kernel<<<T_DIM, 128>>>(h, ln_w, ln_b, hn);

    // 2) Q, K projections (NT, rounded outputs); V projection writes vt
    //    directly via transposed epilogue (fused transpose)
    dim3 gProj(D_DIM / 128, T_DIM / 128);  // (4, 64)
    gemm_nt_tc<0,0,1,0,0,0,0><<<gProj, 128, SM_TOT>>>(hn, nullptr, wq_r, q, nullptr,
        T_DIM, D_DIM, D_DIM, D_DIM, D_DIM, D_DIM, 1.0f);
    gemm_nt_tc<0,0,1,0,0,0,0><<<gProj, 128, SM_TOT>>>(hn, nullptr, wk_r, k, nullptr,
        T_DIM, D_DIM, D_DIM, D_DIM, D_DIM, D_DIM, 1.0f);
    gemm_nt_tc<0,0,1,0,0,1,0><<<gProj, 128, SM_TOT>>>(hn, nullptr, wv_r, vt, nullptr,
        T_DIM, D_DIM, D_DIM, D_DIM, D_DIM, T_DIM, 1.0f);   // ldc = T_DIM (vt rows)

    // 3) Scores = Q @ K^T * 1/sqrt(d), lower-tri blocks only (NT, causal)
    dim3 gScore(T_DIM / 128, T_DIM / 128);  // (64, 64)
    gemm_nt_tc<1,0,0,0,0,0,0><<<gScore, 128, SM_TOT>>>(q, nullptr, k, S, nullptr,
        T_DIM, T_DIM, D_DIM, D_DIM, D_DIM, T_DIM, inv_sqrt_d);

    // 4) Causal softmax (in place, rounded probs, zero-pads to 128-col)
    softmax_causal<<<T_DIM, 256>>>(S);

    // 5) AV partials = softmax(S) @ Vt^T (NT, k-capped, split-K2, raw)
    dim3 gPV(D_DIM / 128, T_DIM / 128, 2);  // (4, 64, 2)
    gemm_nt_tc<0,1,0,0,2,0,0><<<gPV, 128, SM_TOT>>>(S, nullptr, vt, avp, nullptr,
        T_DIM, D_DIM, T_DIM, T_DIM, T_DIM, D_DIM, 1.0f);

    // 6) out = h + rnd(avp0+avp1) @ W_o^T (fused split-K reduce in A loader)
    gemm_nt_tc<0,0,0,1,0,0,1><<<gProj, 128, SM_TOT>>>(avp, avp + (size_t)T_DIM * D_DIM,
        wo_r, out, h,
        T_DIM, D_DIM, D_DIM, D_DIM, D_DIM, D_DIM, 1.0f);
}

// round 9
// speedup vs baseline: 1.2908x; 1.1631x over previous
#include <cuda_runtime.h>
#include <math.h>
#include <stdint.h>

#define T_DIM 8192
#define D_DIM 512

// Scratch (allocation-free rule: __device__ globals)
__device__ float g_hnorm[T_DIM * D_DIM];
__device__ float g_q[T_DIM * D_DIM];
__device__ float g_k[T_DIM * D_DIM];
__device__ float g_vt[T_DIM * D_DIM];          // V transposed: [d][T]
__device__ float g_avp[4][T_DIM * D_DIM];      // PV split-K partials
__device__ float g_wr[4][D_DIM * D_DIM];       // tf32-rounded weights (q,k,v,o)
__device__ float g_S[(size_t)T_DIM * T_DIM];   // 256 MB score matrix

// ===========================================================================
// Helpers
// ===========================================================================
__device__ __forceinline__ uint32_t smem_u32(const void* p) {
    uint32_t a;
    asm("{ .reg .u64 t; cvta.to.shared.u64 t, %1; cvt.u32.u64 %0, t; }" : "=r"(a) : "l"(p));
    return a;
}
__device__ __forceinline__ float rnd_tf32(float f) {
    uint32_t r;
    asm("cvt.rna.tf32.f32 %0, %1;" : "=r"(r) : "f"(f));
    return __uint_as_float(r);
}
#define SW128(o) ((o) ^ ((((uint32_t)(o)) >> 3) & 0x70))

#define CP_ASYNC16(dst, src) \
    asm volatile("cp.async.cg.shared.global [%0], [%1], 16;" :: "r"(dst), "l"(src) : "memory")
#define CP_COMMIT() asm volatile("cp.async.commit_group;" ::: "memory")
#define CP_WAIT1()  asm volatile("cp.async.wait_group 1;" ::: "memory")

__device__ __forceinline__ void ldsm_x4(uint32_t& r0, uint32_t& r1, uint32_t& r2, uint32_t& r3,
                                        uint32_t addr) {
    asm volatile("ldmatrix.sync.aligned.m8n8.x4.shared.b16 {%0,%1,%2,%3}, [%4];"
                 : "=r"(r0), "=r"(r1), "=r"(r2), "=r"(r3) : "r"(addr));
}

__device__ __forceinline__ void mma_tf32(float* c, const uint32_t* a, const uint32_t* b) {
    asm volatile(
        "mma.sync.aligned.m16n8k8.row.col.f32.tf32.tf32.f32 "
        "{%0,%1,%2,%3}, {%4,%5,%6,%7}, {%8,%9}, {%0,%1,%2,%3};"
        : "+f"(c[0]), "+f"(c[1]), "+f"(c[2]), "+f"(c[3])
        : "r"(a[0]), "r"(a[1]), "r"(a[2]), "r"(a[3]),
          "r"(b[0]), "r"(b[1]));
}

// ===========================================================================
// LayerNorm (one block/row, 128 thr, tf32-rounded output).
// Blocks 0..1023 additionally round the 4 weight matrices into g_wr.
// ===========================================================================
__global__ void ln_kernel(const float* __restrict__ h,
                          const float* __restrict__ w,
                          const float* __restrict__ b,
                          float* __restrict__ out,
                          const float* __restrict__ w0,
                          const float* __restrict__ w1,
                          const float* __restrict__ w2,
                          const float* __restrict__ w3,
                          float* __restrict__ wr)
{
    int row = blockIdx.x;
    int t = threadIdx.x;

    // side job: weight rounding (first 1024 blocks, 2 float4 per thread)
    if (row < 1024) {
        #pragma unroll
        for (int j = 0; j < 2; j++) {
            int idx = row * 256 + j * 128 + t;      // float4 index, 0..262143
            int mat = idx >> 16;                    // 65536 float4 per matrix
            int off = idx & 65535;
            const float* src = (mat == 0) ? w0 : (mat == 1) ? w1
                             : (mat == 2) ? w2 : w3;
            float4 v = ((const float4*)src)[off];
            float4 o;
            o.x = rnd_tf32(v.x); o.y = rnd_tf32(v.y);
            o.z = rnd_tf32(v.z); o.w = rnd_tf32(v.w);
            ((float4*)wr)[(size_t)mat * 65536 + off] = o;
        }
    }

    const float4* hr = (const float4*)(h + (size_t)row * D_DIM);
    float4 x = hr[t];
    float s  = x.x + x.y + x.z + x.w;
    float ss = x.x * x.x + x.y * x.y + x.z * x.z + x.w * x.w;

    #pragma unroll
    for (int o = 16; o; o >>= 1) {
        s  += __shfl_xor_sync(0xffffffffu, s,  o);
        ss += __shfl_xor_sync(0xffffffffu, ss, o);
    }
    __shared__ float red[2][4];
    int lane = t & 31, warp = t >> 5;
    if (lane == 0) { red[0][warp] = s; red[1][warp] = ss; }
    __syncthreads();
    float a = red[0][0] + red[0][1] + red[0][2] + red[0][3];
    float c = red[1][0] + red[1][1] + red[1][2] + red[1][3];
    float mean = a * (1.0f / D_DIM);
    float var  = c * (1.0f / D_DIM) - mean * mean;
    float rstd = rsqrtf(var + 1e-5f);

    float4 wv = ((const float4*)w)[t];
    float4 bv = ((const float4*)b)[t];
    float4 o;
    o.x = rnd_tf32((x.x - mean) * rstd * wv.x + bv.x);
    o.y = rnd_tf32((x.y - mean) * rstd * wv.y + bv.y);
    o.z = rnd_tf32((x.z - mean) * rstd * wv.z + bv.z);
    o.w = rnd_tf32((x.w - mean) * rstd * wv.w + bv.w);
    ((float4*)(out + (size_t)row * D_DIM))[t] = o;
}

// ===========================================================================
// TF32 mma.sync GEMM (NT): C = scale*(A[M,K] @ B[N,K]^T) (+res)
// 128x128x32 block tile, 4 warps (2x2), warp tile 64x64, 2 CTA/SM.
// 3-stage cp.async ring, SW128 swizzle, ldmatrix frags.
//   CAUSAL:  skip blocks fully above diagonal
//   CAPK:    cap k-loop at m0+128 (PV); also reverses y-order (big CTAs first)
//   ROUND:   round outputs to tf32 grid
//   RES:     add residual
//   KSPLIT>0: split capped k-range across blockIdx.z, raw partial to
//             C + z*M*ldc
//   QKV:     blockIdx.z in {0,1,2} selects weight B+z*D*D and output
//             {C, C2, C3}; z==2 writes transposed (vt, row stride ldct)
//   SUM4:    A operand = rnd_tf32(sum of 4 partials at A + j*M*lda)
// ===========================================================================
#define BK 32
#define TILE_B (128 * BK * 4)    // 16 KB per tile buffer
#define NSTAGE 3
#define SM_A 0
#define SM_B (NSTAGE * TILE_B)
#define SM_TOT (2 * NSTAGE * TILE_B)   // 96 KB

template<int CAUSAL, int CAPK, int ROUND, int RES, int KSPLIT, int QKV, int SUM4>
__global__ void __launch_bounds__(128, 2)
gemm_nt_tc(const float* __restrict__ A,
           const float* __restrict__ B,
           float* __restrict__ C,
           float* __restrict__ C2,
           float* __restrict__ C3,
           const float* __restrict__ res,
           int M, int N, int K,
           int lda, int ldb, int ldc, int ldct,
           float scale)
{
    extern __shared__ char smem[];
    int yb = CAPK ? ((int)gridDim.y - 1 - (int)blockIdx.y) : (int)blockIdx.y;
    int m0 = yb * 128;
    int n0 = blockIdx.x * 128;
    if (CAUSAL && n0 > m0 + 127) return;

    const float* Bp = B;
    float* Cp = C;
    int ldcw = ldc;
    int zq = 0;
    if (QKV) {
        zq = blockIdx.z;
        Bp = B + (size_t)zq * D_DIM * D_DIM;
        Cp = (zq == 0) ? C : (zq == 1) ? C2 : C3;
        if (zq == 2) ldcw = ldct;
    }

    uint32_t sbase = smem_u32(smem);
    int t    = threadIdx.x;          // 0..127
    int lane = t & 31;
    int warp = t >> 5;               // 0..3
    int gid  = lane >> 2;
    int tig  = lane & 3;
    int wm   = (warp >> 1) * 64;     // 0,64
    int wn   = (warp & 1) * 64;      // 0,64

    int kend  = CAPK ? min(K, m0 + 128) : K;
    int iters = kend / BK;
    int it0 = 0, it1 = iters;
    if (KSPLIT > 0) {
        int z = blockIdx.z;
        it0 = (iters * z) / KSPLIT;
        it1 = (iters * (z + 1)) / KSPLIT;
        Cp = C + (size_t)z * M * ldc;
    }
    int niter = it1 - it0;

    auto load_tiles = [&](int buf, int k0) {
        if (SUM4) {
            #pragma unroll
            for (int i = 0; i < 8; i++) {
                int f = t + i * 128;
                int row = f >> 3, kg = f & 7;
                size_t gidx = (size_t)(m0 + row) * lda + k0 + kg * 4;
                float4 s0 = *(const float4*)(A + gidx);
                float4 s1 = *(const float4*)(A + (size_t)M * lda + gidx);
                float4 s2 = *(const float4*)(A + 2 * (size_t)M * lda + gidx);
                float4 s3 = *(const float4*)(A + 3 * (size_t)M * lda + gidx);
                float4 o;
                o.x = rnd_tf32((s0.x + s1.x) + (s2.x + s3.x));
                o.y = rnd_tf32((s0.y + s1.y) + (s2.y + s3.y));
                o.z = rnd_tf32((s0.z + s1.z) + (s2.z + s3.z));
                o.w = rnd_tf32((s0.w + s1.w) + (s2.w + s3.w));
                uint32_t off = SW128((uint32_t)(row * 128 + kg * 16));
                *(float4*)(smem + SM_A + buf * TILE_B + off) = o;
            }
        } else {
            #pragma unroll
            for (int i = 0; i < 8; i++) {
                int f = t + i * 128;
                int row = f >> 3, kg = f & 7;
                uint32_t off = SW128((uint32_t)(row * 128 + kg * 16));
                CP_ASYNC16(sbase + SM_A + buf * TILE_B + off,
                           A + (size_t)(m0 + row) * lda + k0 + kg * 4);
            }
        }
        #pragma unroll
        for (int i = 0; i < 8; i++) {
            int f = t + i * 128;
            int row = f >> 3, kg = f & 7;
            uint32_t off = SW128((uint32_t)(row * 128 + kg * 16));
            CP_ASYNC16(sbase + SM_B + buf * TILE_B + off,
                       Bp + (size_t)(n0 + row) * ldb + k0 + kg * 4);
        }
    };

    float acc[4][8][4];
    #pragma unroll
    for (int mi = 0; mi < 4; mi++)
        #pragma unroll
        for (int ni = 0; ni < 8; ni++)
            #pragma unroll
            for (int r = 0; r < 4; r++) acc[mi][ni][r] = 0.0f;

    // per-thread ldmatrix address components
    int q   = lane >> 3;
    int r8  = lane & 7;
    int aq1 = (q & 1) * 8;
    int aq2 = q >> 1;
    int bq1 = (q >> 1) * 8;
    int bq2 = q & 1;

    load_tiles(0, it0 * BK);
    CP_COMMIT();
    if (niter > 1) load_tiles(1, (it0 + 1) * BK);
    CP_COMMIT();

    int buf = 0;
    for (int it = 0; it < niter; it++) {
        CP_WAIT1();
        __syncthreads();

        uint32_t sa = sbase + SM_A + buf * TILE_B;
        uint32_t sb = sbase + SM_B + buf * TILE_B;

        int nx = it + 2;
        int nbuf = buf + 2; if (nbuf >= NSTAGE) nbuf -= NSTAGE;
        if (nx < niter) load_tiles(nbuf, (it0 + nx) * BK);
        CP_COMMIT();

        #pragma unroll
        for (int ks = 0; ks < BK / 8; ks++) {
            uint32_t afr[4][4];
            #pragma unroll
            for (int mi = 0; mi < 4; mi++) {
                int row = wm + mi * 16 + aq1 + r8;
                int kg  = 2 * ks + aq2;
                uint32_t addr = sa + (uint32_t)(row * 128) + (uint32_t)((kg ^ r8) * 16);
                ldsm_x4(afr[mi][0], afr[mi][1], afr[mi][2], afr[mi][3], addr);
            }
            uint32_t bfr[8][2];
            #pragma unroll
            for (int p = 0; p < 4; p++) {
                int row = wn + p * 16 + bq1 + r8;
                int kg  = 2 * ks + bq2;
                uint32_t addr = sb + (uint32_t)(row * 128) + (uint32_t)((kg ^ r8) * 16);
                uint32_t r0, r1, r2, r3;
                ldsm_x4(r0, r1, r2, r3, addr);
                bfr[2 * p][0] = r0; bfr[2 * p][1] = r1;
                bfr[2 * p + 1][0] = r2; bfr[2 * p + 1][1] = r3;
            }
            #pragma unroll
            for (int mi = 0; mi < 4; mi++)
                #pragma unroll
                for (int ni = 0; ni < 8; ni++)
                    mma_tf32(acc[mi][ni], afr[mi], bfr[ni]);
        }

        buf++; if (buf >= NSTAGE) buf = 0;
    }

    if (QKV && zq == 2) {
        // Transposed output: stage tile transposed in smem, coalesced float4
        // writes of C[n][m] rows. Rounded to tf32 grid.
        __syncthreads();
        float* st = (float*)smem;        // 128 x stride 132
        #pragma unroll
        for (int mi = 0; mi < 4; mi++) {
            #pragma unroll
            for (int ni = 0; ni < 8; ni++) {
                int row = wm + mi * 16 + gid;
                int col = wn + ni * 8 + tig * 2;
                st[(col + 0) * 132 + row]     = rnd_tf32(acc[mi][ni][0]);
                st[(col + 1) * 132 + row]     = rnd_tf32(acc[mi][ni][1]);
                st[(col + 0) * 132 + row + 8] = rnd_tf32(acc[mi][ni][2]);
                st[(col + 1) * 132 + row + 8] = rnd_tf32(acc[mi][ni][3]);
            }
        }
        __syncthreads();
        #pragma unroll
        for (int i = 0; i < 32; i++) {
            int idx = t + i * 128;
            int d = idx >> 5;
            int j = idx & 31;
            float4 o = *(float4*)&st[d * 132 + 4 * j];
            *(float4*)(Cp + (size_t)(n0 + d) * ldcw + m0 + 4 * j) = o;
        }
        return;
    }

    // normal epilogue
    #pragma unroll
    for (int mi = 0; mi < 4; mi++) {
        #pragma unroll
        for (int ni = 0; ni < 8; ni++) {
            int row = m0 + wm + mi * 16 + gid;
            int col = n0 + wn + ni * 8 + tig * 2;
            float2 o0, o1;
            o0.x = acc[mi][ni][0]; o0.y = acc[mi][ni][1];
            o1.x = acc[mi][ni][2]; o1.y = acc[mi][ni][3];
            if (!KSPLIT) {
                o0.x *= scale; o0.y *= scale; o1.x *= scale; o1.y *= scale;
            }
            size_t i0 = (size_t)row * ldcw + col;
            size_t i1 = (size_t)(row + 8) * ldcw + col;
            if (RES) {
                float2 r0 = *(const float2*)(res + i0);
                float2 r1 = *(const float2*)(res + i1);
                o0.x += r0.x; o0.y += r0.y;
                o1.x += r1.x; o1.y += r1.y;
            }
            if (ROUND) {
                o0.x = rnd_tf32(o0.x); o0.y = rnd_tf32(o0.y);
                o1.x = rnd_tf32(o1.x); o1.y = rnd_tf32(o1.y);
            }
            *(float2*)(Cp + i0) = o0;
            *(float2*)(Cp + i1) = o1;
        }
    }
}

// ===========================================================================
// Causal row softmax over S (in place), float4 + __expf.
// Output probs rounded to tf32 grid; zero-pads to next 128-col boundary.
// ===========================================================================
__device__ __forceinline__ float block_reduce(float v, bool is_max)
{
    __shared__ float sm[8];
    __syncthreads();
    #pragma unroll
    for (int o = 16; o; o >>= 1) {
        float u = __shfl_xor_sync(0xffffffffu, v, o);
        v = is_max ? fmaxf(v, u) : (v + u);
    }
    int lane = threadIdx.x & 31, warp = threadIdx.x >> 5;
    if (lane == 0) sm[warp] = v;
    __syncthreads();
    float r = sm[0];
    #pragma unroll
    for (int i = 1; i < 8; i++)
        r = is_max ? fmaxf(r, sm[i]) : (r + sm[i]);
    return r;
}

__global__ void softmax_causal(float* __restrict__ S)
{
    int row = blockIdx.x;
    int t = threadIdx.x;               // 0..255
    int n = row + 1;
    float4* Srow = (float4*)(S + (size_t)row * T_DIM);

    float4 v[8];
    float mx = -INFINITY;
    #pragma unroll
    for (int it = 0; it < 8; it++) {
        int j0 = ((it << 8) + t) << 2;
        float4 x = (j0 < n) ? Srow[(it << 8) + t]
                            : make_float4(-INFINITY, -INFINITY, -INFINITY, -INFINITY);
        if (j0 + 1 >= n) x.y = -INFINITY;
        if (j0 + 2 >= n) x.z = -INFINITY;
        if (j0 + 3 >= n) x.w = -INFINITY;
        v[it] = x;
        mx = fmaxf(mx, fmaxf(fmaxf(x.x, x.y), fmaxf(x.z, x.w)));
    }
    mx = block_reduce(mx, true);

    float sum = 0.0f;
    #pragma unroll
    for (int it = 0; it < 8; it++) {
        float4 x = v[it];
        x.x = (x.x == -INFINITY) ? 0.0f : __expf(x.x - mx);
        x.y = (x.y == -INFINITY) ? 0.0f : __expf(x.y - mx);
        x.z = (x.z == -INFINITY) ? 0.0f : __expf(x.z - mx);
        x.w = (x.w == -INFINITY) ? 0.0f : __expf(x.w - mx);
        v[it] = x;
        sum += x.x + x.y + x.z + x.w;
    }
    sum = block_reduce(sum, false);
    float inv = 1.0f / sum;

    int zend = (n + 127) & ~127;
    #pragma unroll
    for (int it = 0; it < 8; it++) {
        int j0 = ((it << 8) + t) << 2;
        if (j0 < zend) {
            float4 x = v[it];
            float4 o;
            o.x = rnd_tf32(x.x * inv);
            o.y = rnd_tf32(x.y * inv);
            o.z = rnd_tf32(x.z * inv);
            o.w = rnd_tf32(x.w * inv);
            Srow[(it << 8) + t] = o;
        }
    }
}

// ===========================================================================
extern "C" void kernel_launch(void* const* d_in, const int* in_sizes, int n_in,
                              void* d_out, int out_size)
{
    const float* h    = (const float*)d_in[0];
    const float* ln_w = (const float*)d_in[1];
    const float* ln_b = (const float*)d_in[2];
    const float* w_q  = (const float*)d_in[3];
    const float* w_k  = (const float*)d_in[4];
    const float* w_v  = (const float*)d_in[5];
    const float* w_o  = (const float*)d_in[6];
    float* out = (float*)d_out;

    float *hn, *q, *k, *vt, *avp, *S, *wr;
    cudaGetSymbolAddress((void**)&hn,  g_hnorm);
    cudaGetSymbolAddress((void**)&q,   g_q);
    cudaGetSymbolAddress((void**)&k,   g_k);
    cudaGetSymbolAddress((void**)&vt,  g_vt);
    cudaGetSymbolAddress((void**)&avp, g_avp);
    cudaGetSymbolAddress((void**)&S,   g_S);
    cudaGetSymbolAddress((void**)&wr,  g_wr);
    float* wo_r = wr + 3 * (size_t)D_DIM * D_DIM;

    cudaFuncSetAttribute((const void*)gemm_nt_tc<0,0,1,0,0,1,0>,
                         cudaFuncAttributeMaxDynamicSharedMemorySize, SM_TOT);
    cudaFuncSetAttribute((const void*)gemm_nt_tc<1,0,0,0,0,0,0>,
                         cudaFuncAttributeMaxDynamicSharedMemorySize, SM_TOT);
    cudaFuncSetAttribute((const void*)gemm_nt_tc<0,1,0,0,4,0,0>,
                         cudaFuncAttributeMaxDynamicSharedMemorySize, SM_TOT);
    cudaFuncSetAttribute((const void*)gemm_nt_tc<0,0,0,1,0,0,1>,
                         cudaFuncAttributeMaxDynamicSharedMemorySize, SM_TOT);

    const float inv_sqrt_d = 0.044194173824159216f;  // 1/sqrt(512)

    // 1) LayerNorm (+ fused weight rounding into g_wr)
    ln_kernel<<<T_DIM, 128>>>(h, ln_w, ln_b, hn, w_q, w_k, w_v, w_o, wr);

    // 2) Q, K, V projections in ONE launch (z selects; z=2 writes vt transposed)
    dim3 gQKV(D_DIM / 128, T_DIM / 128, 3);  // (4, 64, 3) = 768 CTAs
    gemm_nt_tc<0,0,1,0,0,1,0><<<gQKV, 128, SM_TOT>>>(hn, wr, q, k, vt, nullptr,
        T_DIM, D_DIM, D_DIM, D_DIM, D_DIM, D_DIM, T_DIM, 1.0f);

    // 3) Scores = Q @ K^T * 1/sqrt(d), lower-tri blocks only (NT, causal)
    dim3 gScore(T_DIM / 128, T_DIM / 128);  // (64, 64)
    gemm_nt_tc<1,0,0,0,0,0,0><<<gScore, 128, SM_TOT>>>(q, k, S, nullptr, nullptr, nullptr,
        T_DIM, T_DIM, D_DIM, D_DIM, D_DIM, T_DIM, 0, inv_sqrt_d);

    // 4) Causal softmax (in place, rounded probs, zero-pads to 128-col)
    softmax_causal<<<T_DIM, 256>>>(S);

    // 5) AV partials = softmax(S) @ Vt^T (NT, k-capped, split-K4, big CTAs first)
    dim3 gPV(D_DIM / 128, T_DIM / 128, 4);  // (4, 64, 4) = 1024 CTAs
    gemm_nt_tc<0,1,0,0,4,0,0><<<gPV, 128, SM_TOT>>>(S, vt, avp, nullptr, nullptr, nullptr,
        T_DIM, D_DIM, T_DIM, T_DIM, T_DIM, D_DIM, 0, 1.0f);

    // 6) out = h + rnd(sum of 4 partials) @ W_o^T (fused reduce in A loader)
    dim3 gProj(D_DIM / 128, T_DIM / 128);  // (4, 64)
    gemm_nt_tc<0,0,0,1,0,0,1><<<gProj, 128, SM_TOT>>>(avp, wo_r, out, nullptr, nullptr, h,
        T_DIM, D_DIM, D_DIM, D_DIM, D_DIM, D_DIM, 0, 1.0f);
}